// round 5
// baseline (speedup 1.0000x reference)
#include <cuda_runtime.h>
#include <cuda_bf16.h>

#define BB 32
#define TT 1024
#define HH 384
#define MEL 4096
#define H4 (HH/4)   // 96 float4 per frame
#define GG 8        // tokens per expand block
#define NTB (TT/GG) // 128 token-blocks per batch
#define ZB 64       // zerofill blocks per batch (appended to expand grid)

// scratch (allocation-free rule: device globals)
__device__ int g_start[BB * TT];   // exclusive cumsum of reps
__device__ int g_dec[BB];

// ---------------------------------------------------------------------------
// Kernel 1: per-batch scan -> start offsets, dec_lens, and the output tail
// ---------------------------------------------------------------------------
__global__ void __launch_bounds__(TT) prep_kernel(const int* __restrict__ durations,
                                                  float* __restrict__ out_tail)
{
    const int b = blockIdx.x;
    const int t = threadIdx.x;
    const int lane = t & 31;
    const int wid  = t >> 5;

    int rep = durations[b * TT + t];   // PACE==1.0, ints: round(d/1)=d
    if (rep < 0) rep = 0;

    // warp inclusive scan
    int v = rep;
    #pragma unroll
    for (int o = 1; o < 32; o <<= 1) {
        int n = __shfl_up_sync(0xFFFFFFFFu, v, o);
        if (lane >= o) v += n;
    }

    __shared__ int wsum[32];
    __shared__ int s_total;
    if (lane == 31) wsum[wid] = v;
    __syncthreads();
    if (wid == 0) {
        int s = wsum[lane];
        #pragma unroll
        for (int o = 1; o < 32; o <<= 1) {
            int n = __shfl_up_sync(0xFFFFFFFFu, s, o);
            if (lane >= o) s += n;
        }
        wsum[lane] = s;
    }
    __syncthreads();

    const int csum = v + (wid > 0 ? wsum[wid - 1] : 0);  // inclusive
    if (t == TT - 1) s_total = csum;
    __syncthreads();

    g_start[b * TT + t] = csum - rep;                    // exclusive
    if (t == 0) {
        const int dlen = min(s_total, MEL);
        g_dec[b] = dlen;
        if (out_tail) out_tail[b] = (float)dlen;
    }
}

// ---------------------------------------------------------------------------
// Kernel 2: GG tokens per block; weights cached in registers; enc prefetched.
// grid = (NTB + ZB, BB), 96 threads (one float4 slot each).
//   blockIdx.x <  NTB : token expansion (tokens [x*GG, x*GG+GG))
//   blockIdx.x >= NTB : zero the [dec_len, MEL) tail (strided over ZB blocks)
// ---------------------------------------------------------------------------
__global__ void __launch_bounds__(96) expand_kernel(
    const float* __restrict__ enc,     // [B,T,H]
    const float* __restrict__ pitch,   // [B,1,T]
    const float* __restrict__ energy,  // [B,1,T]
    const float* __restrict__ pw,      // [H,1,3]
    const float* __restrict__ pb,      // [H]
    const float* __restrict__ ew,      // [H,1,3]
    const float* __restrict__ eb,      // [H]
    const int*   __restrict__ durations,
    float* __restrict__ out)           // [B,MEL,H]
{
    const int b = blockIdx.y;
    const int q = threadIdx.x;

    if (blockIdx.x >= NTB) {
        // ---- zerofill path ----
        const int z = blockIdx.x - NTB;
        const int dec = g_dec[b];
        const float4 zero = make_float4(0.f, 0.f, 0.f, 0.f);
        float4* base = (float4*)out + (long long)b * MEL * H4 + q;
        for (int j = dec + z; j < MEL; j += ZB)
            __stcs(base + (long long)j * H4, zero);
        return;
    }

    const int t0 = blockIdx.x * GG;

    // per-block uniform metadata for all GG tokens
    const int* durB  = durations + b * TT + t0;
    const int* strB  = g_start   + b * TT + t0;

    // weights: loaded ONCE per block into registers
    const float4* pwv = (const float4*)(pw + 12 * q);
    const float4 w0 = pwv[0], w1 = pwv[1], w2 = pwv[2];
    const float4* ewv = (const float4*)(ew + 12 * q);
    const float4 u0 = ewv[0], u1 = ewv[1], u2 = ewv[2];
    const float4 pbv = ((const float4*)pb)[q];
    const float4 ebv = ((const float4*)eb)[q];
    const float bias_x = pbv.x + ebv.x, bias_y = pbv.y + ebv.y;
    const float bias_z = pbv.z + ebv.z, bias_w = pbv.w + ebv.w;

    const float* encB = enc + ((long long)b * TT + t0) * HH + 4 * q;
    const float* pr = pitch  + (long long)b * TT;
    const float* er = energy + (long long)b * TT;

    // prefetch enc row for first token
    float4 e_next = *(const float4*)encB;

    #pragma unroll
    for (int g = 0; g < GG; ++g) {
        const int t = t0 + g;
        const float4 e4 = e_next;
        if (g + 1 < GG)
            e_next = *(const float4*)(encB + (g + 1) * HH);

        const int rep   = durB[g];
        if (rep <= 0) continue;
        const int start = strB[g];
        const int end   = min(start + rep, MEL);
        if (start >= end) continue;

        // conv windows (SAME, zero pad) — broadcast loads, L1-resident
        const float pm1 = (t > 0)      ? pr[t - 1] : 0.f;
        const float p0  =                pr[t];
        const float pp1 = (t < TT - 1) ? pr[t + 1] : 0.f;
        const float em1 = (t > 0)      ? er[t - 1] : 0.f;
        const float e0  =                er[t];
        const float ep1 = (t < TT - 1) ? er[t + 1] : 0.f;

        float4 res;
        res.x = e4.x + bias_x
              + pm1 * w0.x + p0 * w0.y + pp1 * w0.z
              + em1 * u0.x + e0 * u0.y + ep1 * u0.z;
        res.y = e4.y + bias_y
              + pm1 * w0.w + p0 * w1.x + pp1 * w1.y
              + em1 * u0.w + e0 * u1.x + ep1 * u1.y;
        res.z = e4.z + bias_z
              + pm1 * w1.z + p0 * w1.w + pp1 * w2.x
              + em1 * u1.z + e0 * u1.w + ep1 * u2.x;
        res.w = e4.w + bias_w
              + pm1 * w2.y + p0 * w2.z + pp1 * w2.w
              + em1 * u2.y + e0 * u2.z + ep1 * u2.w;

        // stream to the rep contiguous frames (coalesced STG.128, evict-first)
        float4* dst = (float4*)out + ((long long)b * MEL + start) * H4 + q;
        #pragma unroll 4
        for (int j = start; j < end; ++j, dst += H4)
            __stcs(dst, res);
    }
}

extern "C" void kernel_launch(void* const* d_in, const int* in_sizes, int n_in,
                              void* d_out, int out_size)
{
    const float* enc    = (const float*)d_in[0];
    const float* pitch  = (const float*)d_in[1];
    const float* energy = (const float*)d_in[2];
    const float* pw     = (const float*)d_in[3];
    const float* pb     = (const float*)d_in[4];
    const float* ew     = (const float*)d_in[5];
    const float* eb     = (const float*)d_in[6];
    const int*   dur    = (const int*)d_in[7];
    float* out = (float*)d_out;

    const long long mainN = (long long)BB * MEL * HH;    // 50,331,648
    float* out_tail = ((long long)out_size >= mainN + BB) ? (out + mainN) : nullptr;

    prep_kernel<<<BB, TT>>>(dur, out_tail);

    dim3 egrid(NTB + ZB, BB);
    expand_kernel<<<egrid, 96>>>(enc, pitch, energy, pw, pb, ew, eb, dur, out);
}

// round 6
// speedup vs baseline: 1.0973x; 1.0973x over previous
#include <cuda_runtime.h>
#include <cuda_bf16.h>

#define BB 32
#define TT 1024
#define HH 384
#define MEL 4096
#define H4 (HH/4)   // 96 float4 per frame
#define ZB 128      // zerofill blocks per batch (appended to expand grid)

// scratch (allocation-free rule: device globals)
__device__ int g_start[BB * TT];   // exclusive cumsum of reps
__device__ int g_dec[BB];

// ---------------------------------------------------------------------------
// Kernel 1: per-batch scan -> start offsets, dec_lens, and the output tail
// ---------------------------------------------------------------------------
__global__ void __launch_bounds__(TT) prep_kernel(const int* __restrict__ durations,
                                                  float* __restrict__ out_tail)
{
    const int b = blockIdx.x;
    const int t = threadIdx.x;
    const int lane = t & 31;
    const int wid  = t >> 5;

    int rep = durations[b * TT + t];   // PACE==1.0, ints: round(d/1)=d
    if (rep < 0) rep = 0;

    // warp inclusive scan
    int v = rep;
    #pragma unroll
    for (int o = 1; o < 32; o <<= 1) {
        int n = __shfl_up_sync(0xFFFFFFFFu, v, o);
        if (lane >= o) v += n;
    }

    __shared__ int wsum[32];
    __shared__ int s_total;
    if (lane == 31) wsum[wid] = v;
    __syncthreads();
    if (wid == 0) {
        int s = wsum[lane];
        #pragma unroll
        for (int o = 1; o < 32; o <<= 1) {
            int n = __shfl_up_sync(0xFFFFFFFFu, s, o);
            if (lane >= o) s += n;
        }
        wsum[lane] = s;
    }
    __syncthreads();

    const int csum = v + (wid > 0 ? wsum[wid - 1] : 0);  // inclusive
    if (t == TT - 1) s_total = csum;
    __syncthreads();

    g_start[b * TT + t] = csum - rep;                    // exclusive
    if (t == 0) {
        const int dlen = min(s_total, MEL);
        g_dec[b] = dlen;
        if (out_tail) out_tail[b] = (float)dlen;
    }
}

// ---------------------------------------------------------------------------
// Kernel 2: one token per block, 96 threads (one float4 slot each).
//   blockIdx.x <  TT : token expansion, predicated 7-wide store burst
//   blockIdx.x >= TT : zero the [dec_len, MEL) tail (strided over ZB blocks)
// ---------------------------------------------------------------------------
__global__ void __launch_bounds__(96) expand_kernel(
    const float* __restrict__ enc,     // [B,T,H]
    const float* __restrict__ pitch,   // [B,1,T]
    const float* __restrict__ energy,  // [B,1,T]
    const float* __restrict__ pw,      // [H,1,3]
    const float* __restrict__ pb,      // [H]
    const float* __restrict__ ew,      // [H,1,3]
    const float* __restrict__ eb,      // [H]
    const int*   __restrict__ durations,
    float* __restrict__ out)           // [B,MEL,H]
{
    const int b = blockIdx.y;
    const int q = threadIdx.x;

    if (blockIdx.x >= TT) {
        // ---- zerofill path ----
        const int z = blockIdx.x - TT;
        const int dec = g_dec[b];
        const float4 zero = make_float4(0.f, 0.f, 0.f, 0.f);
        float4* base = (float4*)out + (long long)b * MEL * H4 + q;
        for (int j = dec + z; j < MEL; j += ZB)
            __stcs(base + (long long)j * H4, zero);
        return;
    }

    const int t = blockIdx.x;
    const int rep = durations[b * TT + t];
    if (rep <= 0) return;
    const int start = g_start[b * TT + t];
    const int n = min(start + rep, MEL) - start;
    if (n <= 0) return;

    // enc row (one float4 per thread)
    const float4 e4 = *(const float4*)(enc + ((long long)b * TT + t) * HH + 4 * q);

    // conv windows (SAME, zero pad) — broadcast loads, L1/L2-resident
    const float* pr = pitch  + (long long)b * TT;
    const float* er = energy + (long long)b * TT;
    const float pm1 = (t > 0)      ? pr[t - 1] : 0.f;
    const float p0  =                pr[t];
    const float pp1 = (t < TT - 1) ? pr[t + 1] : 0.f;
    const float em1 = (t > 0)      ? er[t - 1] : 0.f;
    const float e0  =                er[t];
    const float ep1 = (t < TT - 1) ? er[t + 1] : 0.f;

    // weights: [H][3] row-major -> 12 contiguous floats per float4-slot
    const float4* pwv = (const float4*)(pw + 12 * q);
    const float4 w0 = pwv[0], w1 = pwv[1], w2 = pwv[2];
    const float4* ewv = (const float4*)(ew + 12 * q);
    const float4 u0 = ewv[0], u1 = ewv[1], u2 = ewv[2];
    const float4 pbv = ((const float4*)pb)[q];
    const float4 ebv = ((const float4*)eb)[q];

    float4 res;
    res.x = e4.x + pbv.x + ebv.x
          + pm1 * w0.x + p0 * w0.y + pp1 * w0.z
          + em1 * u0.x + e0 * u0.y + ep1 * u0.z;
    res.y = e4.y + pbv.y + ebv.y
          + pm1 * w0.w + p0 * w1.x + pp1 * w1.y
          + em1 * u0.w + e0 * u1.x + ep1 * u1.y;
    res.z = e4.z + pbv.z + ebv.z
          + pm1 * w1.z + p0 * w1.w + pp1 * w2.x
          + em1 * u1.z + e0 * u1.w + ep1 * u2.x;
    res.w = e4.w + pbv.w + ebv.w
          + pm1 * w2.y + p0 * w2.z + pp1 * w2.w
          + em1 * u2.y + e0 * u2.z + ep1 * u2.w;

    // predicated store burst: reps < 8, all addresses independent,
    // stores issue back-to-back with no loop-carried dependency
    float4* dst = (float4*)out + ((long long)b * MEL + start) * H4 + q;
    #pragma unroll
    for (int j = 0; j < 7; ++j)
        if (j < n) __stcs(dst + (long long)j * H4, res);
    for (int j = 7; j < n; ++j)          // safety; never taken for this data
        __stcs(dst + (long long)j * H4, res);
}

extern "C" void kernel_launch(void* const* d_in, const int* in_sizes, int n_in,
                              void* d_out, int out_size)
{
    const float* enc    = (const float*)d_in[0];
    const float* pitch  = (const float*)d_in[1];
    const float* energy = (const float*)d_in[2];
    const float* pw     = (const float*)d_in[3];
    const float* pb     = (const float*)d_in[4];
    const float* ew     = (const float*)d_in[5];
    const float* eb     = (const float*)d_in[6];
    const int*   dur    = (const int*)d_in[7];
    float* out = (float*)d_out;

    const long long mainN = (long long)BB * MEL * HH;    // 50,331,648
    float* out_tail = ((long long)out_size >= mainN + BB) ? (out + mainN) : nullptr;

    prep_kernel<<<BB, TT>>>(dur, out_tail);

    dim3 egrid(TT + ZB, BB);
    expand_kernel<<<egrid, 96>>>(enc, pitch, energy, pw, pb, ew, eb, dur, out);
}

// round 7
// speedup vs baseline: 1.1411x; 1.0399x over previous
#include <cuda_runtime.h>
#include <cuda_bf16.h>

#define BB 32
#define TT 1024
#define HH 384
#define MEL 4096
#define H4 (HH/4)   // 96 float4 per frame
#define ZB 128      // zerofill blocks per batch (appended to expand grid)

// scratch (allocation-free rule: device globals)
__device__ int g_start[BB * TT];   // exclusive cumsum of reps
__device__ int g_dec[BB];

// ---------------------------------------------------------------------------
// Kernel 1: per-batch scan -> start offsets, dec_lens, and the output tail
// ---------------------------------------------------------------------------
__global__ void __launch_bounds__(TT) prep_kernel(const int* __restrict__ durations,
                                                  float* __restrict__ out_tail)
{
    const int b = blockIdx.x;
    const int t = threadIdx.x;
    const int lane = t & 31;
    const int wid  = t >> 5;

    int rep = durations[b * TT + t];   // PACE==1.0, ints: round(d/1)=d
    if (rep < 0) rep = 0;

    // warp inclusive scan
    int v = rep;
    #pragma unroll
    for (int o = 1; o < 32; o <<= 1) {
        int n = __shfl_up_sync(0xFFFFFFFFu, v, o);
        if (lane >= o) v += n;
    }

    __shared__ int wsum[32];
    __shared__ int s_total;
    if (lane == 31) wsum[wid] = v;
    __syncthreads();
    if (wid == 0) {
        int s = wsum[lane];
        #pragma unroll
        for (int o = 1; o < 32; o <<= 1) {
            int n = __shfl_up_sync(0xFFFFFFFFu, s, o);
            if (lane >= o) s += n;
        }
        wsum[lane] = s;
    }
    __syncthreads();

    const int csum = v + (wid > 0 ? wsum[wid - 1] : 0);  // inclusive
    if (t == TT - 1) s_total = csum;
    __syncthreads();

    g_start[b * TT + t] = csum - rep;                    // exclusive
    if (t == 0) {
        const int dlen = min(s_total, MEL);
        g_dec[b] = dlen;
        if (out_tail) out_tail[b] = (float)dlen;
    }
}

// ---------------------------------------------------------------------------
// Kernel 2: one token per block, 96 threads (one float4 slot each).
// Launched with programmatic stream serialization (PDL): the prologue
// (everything independent of prep) runs concurrently with prep; we only
// cudaGridDependencySynchronize() right before touching g_start / g_dec.
//   blockIdx.x <  TT : token expansion, predicated 7-wide store burst
//   blockIdx.x >= TT : zero the [dec_len, MEL) tail (strided over ZB blocks)
// ---------------------------------------------------------------------------
__global__ void __launch_bounds__(96) expand_kernel(
    const float* __restrict__ enc,     // [B,T,H]
    const float* __restrict__ pitch,   // [B,1,T]
    const float* __restrict__ energy,  // [B,1,T]
    const float* __restrict__ pw,      // [H,1,3]
    const float* __restrict__ pb,      // [H]
    const float* __restrict__ ew,      // [H,1,3]
    const float* __restrict__ eb,      // [H]
    const int*   __restrict__ durations,
    float* __restrict__ out)           // [B,MEL,H]
{
    const int b = blockIdx.y;
    const int q = threadIdx.x;

    if (blockIdx.x >= TT) {
        // ---- zerofill path ----
        const int z = blockIdx.x - TT;
        const float4 zero = make_float4(0.f, 0.f, 0.f, 0.f);
        float4* base = (float4*)out + (long long)b * MEL * H4 + q;
        cudaGridDependencySynchronize();           // need g_dec
        const int dec = g_dec[b];
        for (int j = dec + z; j < MEL; j += ZB)
            __stcs(base + (long long)j * H4, zero);
        return;
    }

    const int t = blockIdx.x;
    const int rep = durations[b * TT + t];         // input, prep-independent
    if (rep <= 0) return;

    // ---- prep-independent prologue (overlaps with prep under PDL) ----
    // enc row (one float4 per thread)
    const float4 e4 = *(const float4*)(enc + ((long long)b * TT + t) * HH + 4 * q);

    // conv windows (SAME, zero pad) — broadcast loads, L1/L2-resident
    const float* pr = pitch  + (long long)b * TT;
    const float* er = energy + (long long)b * TT;
    const float pm1 = (t > 0)      ? pr[t - 1] : 0.f;
    const float p0  =                pr[t];
    const float pp1 = (t < TT - 1) ? pr[t + 1] : 0.f;
    const float em1 = (t > 0)      ? er[t - 1] : 0.f;
    const float e0  =                er[t];
    const float ep1 = (t < TT - 1) ? er[t + 1] : 0.f;

    // weights: [H][3] row-major -> 12 contiguous floats per float4-slot
    const float4* pwv = (const float4*)(pw + 12 * q);
    const float4 w0 = pwv[0], w1 = pwv[1], w2 = pwv[2];
    const float4* ewv = (const float4*)(ew + 12 * q);
    const float4 u0 = ewv[0], u1 = ewv[1], u2 = ewv[2];
    const float4 pbv = ((const float4*)pb)[q];
    const float4 ebv = ((const float4*)eb)[q];

    float4 res;
    res.x = e4.x + pbv.x + ebv.x
          + pm1 * w0.x + p0 * w0.y + pp1 * w0.z
          + em1 * u0.x + e0 * u0.y + ep1 * u0.z;
    res.y = e4.y + pbv.y + ebv.y
          + pm1 * w0.w + p0 * w1.x + pp1 * w1.y
          + em1 * u0.w + e0 * u1.x + ep1 * u1.y;
    res.z = e4.z + pbv.z + ebv.z
          + pm1 * w1.z + p0 * w1.w + pp1 * w2.x
          + em1 * u1.z + e0 * u1.w + ep1 * u2.x;
    res.w = e4.w + pbv.w + ebv.w
          + pm1 * w2.y + p0 * w2.z + pp1 * w2.w
          + em1 * u2.y + e0 * u2.z + ep1 * u2.w;

    // ---- dependent part: wait for prep, then read start and burst-store ----
    cudaGridDependencySynchronize();
    const int start = g_start[b * TT + t];
    const int n = min(start + rep, MEL) - start;
    if (n <= 0) return;

    // predicated store burst: reps < 8, all addresses independent,
    // stores issue back-to-back with no loop-carried dependency
    float4* dst = (float4*)out + ((long long)b * MEL + start) * H4 + q;
    #pragma unroll
    for (int j = 0; j < 7; ++j)
        if (j < n) __stcs(dst + (long long)j * H4, res);
    for (int j = 7; j < n; ++j)          // safety; never taken for this data
        __stcs(dst + (long long)j * H4, res);
}

extern "C" void kernel_launch(void* const* d_in, const int* in_sizes, int n_in,
                              void* d_out, int out_size)
{
    const float* enc    = (const float*)d_in[0];
    const float* pitch  = (const float*)d_in[1];
    const float* energy = (const float*)d_in[2];
    const float* pw     = (const float*)d_in[3];
    const float* pb     = (const float*)d_in[4];
    const float* ew     = (const float*)d_in[5];
    const float* eb     = (const float*)d_in[6];
    const int*   dur    = (const int*)d_in[7];
    float* out = (float*)d_out;

    const long long mainN = (long long)BB * MEL * HH;    // 50,331,648
    float* out_tail = ((long long)out_size >= mainN + BB) ? (out + mainN) : nullptr;

    prep_kernel<<<BB, TT>>>(dur, out_tail);

    // expand launched with programmatic dependent launch: starts while prep
    // is still running; the device-side sync gates only the g_start/g_dec reads.
    cudaLaunchConfig_t cfg = {};
    cfg.gridDim  = dim3(TT + ZB, BB, 1);
    cfg.blockDim = dim3(96, 1, 1);
    cfg.dynamicSmemBytes = 0;
    cfg.stream = 0;   // legacy default stream (matches harness capture)
    cudaLaunchAttribute attrs[1];
    attrs[0].id = cudaLaunchAttributeProgrammaticStreamSerialization;
    attrs[0].val.programmaticStreamSerializationAllowed = 1;
    cfg.attrs = attrs;
    cfg.numAttrs = 1;
    cudaLaunchKernelEx(&cfg, expand_kernel,
                       enc, pitch, energy, pw, pb, ew, eb, dur, out);
}

// round 8
// speedup vs baseline: 1.1453x; 1.0037x over previous
#include <cuda_runtime.h>
#include <cuda_bf16.h>

#define BB 32
#define TT 1024
#define HH 384
#define MEL 4096
#define H4 (HH/4)   // 96 float4 per frame
#define ZB 128      // zerofill blocks per batch (appended to expand grid)
#define PT 256      // prep threads (each handles 4 tokens via int4)

// scratch (allocation-free rule: device globals)
__device__ int g_start[BB * TT];   // exclusive cumsum of reps
__device__ int g_dec[BB];

// ---------------------------------------------------------------------------
// Kernel 1: per-batch scan -> start offsets, dec_lens, and the output tail.
// 256 threads, int4-vectorized: thread i owns tokens [4i, 4i+4).
// ---------------------------------------------------------------------------
__global__ void __launch_bounds__(PT) prep_kernel(const int* __restrict__ durations,
                                                  float* __restrict__ out_tail)
{
    const int b = blockIdx.x;
    const int i = threadIdx.x;
    const int lane = i & 31;
    const int wid  = i >> 5;

    int4 d = ((const int4*)(durations + b * TT))[i];
    if (d.x < 0) d.x = 0;
    if (d.y < 0) d.y = 0;
    if (d.z < 0) d.z = 0;
    if (d.w < 0) d.w = 0;
    const int local = d.x + d.y + d.z + d.w;

    // warp inclusive scan of per-thread sums
    int v = local;
    #pragma unroll
    for (int o = 1; o < 32; o <<= 1) {
        int n = __shfl_up_sync(0xFFFFFFFFu, v, o);
        if (lane >= o) v += n;
    }

    __shared__ int wsum[8];
    if (lane == 31) wsum[wid] = v;
    __syncthreads();
    // scan the 8 warp totals in warp 0
    if (wid == 0 && lane < 8) {
        int s = wsum[lane];
        #pragma unroll
        for (int o = 1; o < 8; o <<= 1) {
            int n = __shfl_up_sync(0xFFu, s, o);
            if (lane >= o) s += n;
        }
        wsum[lane] = s;
    }
    __syncthreads();

    const int base = (v - local) + (wid > 0 ? wsum[wid - 1] : 0); // exclusive @ token 4i

    int4 st;
    st.x = base;
    st.y = base + d.x;
    st.z = st.y + d.y;
    st.w = st.z + d.z;
    ((int4*)(g_start + b * TT))[i] = st;

    if (i == PT - 1) {
        const int total = st.w + d.w;
        const int dlen = min(total, MEL);
        g_dec[b] = dlen;
        if (out_tail) out_tail[b] = (float)dlen;
    }
}

// ---------------------------------------------------------------------------
// Kernel 2: one token per block, 96 threads (one float4 slot each).
// Launched with programmatic stream serialization (PDL): the prologue
// (everything independent of prep) runs concurrently with prep; we only
// cudaGridDependencySynchronize() right before touching g_start / g_dec.
//   blockIdx.x <  TT : token expansion, predicated 7-wide store burst
//   blockIdx.x >= TT : zero the [dec_len, MEL) tail (strided over ZB blocks)
// ---------------------------------------------------------------------------
__global__ void __launch_bounds__(96) expand_kernel(
    const float* __restrict__ enc,     // [B,T,H]
    const float* __restrict__ pitch,   // [B,1,T]
    const float* __restrict__ energy,  // [B,1,T]
    const float* __restrict__ pw,      // [H,1,3]
    const float* __restrict__ pb,      // [H]
    const float* __restrict__ ew,      // [H,1,3]
    const float* __restrict__ eb,      // [H]
    const int*   __restrict__ durations,
    float* __restrict__ out)           // [B,MEL,H]
{
    const int b = blockIdx.y;
    const int q = threadIdx.x;

    if (blockIdx.x >= TT) {
        // ---- zerofill path ----
        const int z = blockIdx.x - TT;
        const float4 zero = make_float4(0.f, 0.f, 0.f, 0.f);
        float4* base = (float4*)out + (long long)b * MEL * H4 + q;
        cudaGridDependencySynchronize();           // need g_dec
        const int dec = g_dec[b];
        for (int j = dec + z; j < MEL; j += ZB)
            __stcs(base + (long long)j * H4, zero);
        return;
    }

    const int t = blockIdx.x;
    const int rep = durations[b * TT + t];         // input, prep-independent
    if (rep <= 0) return;

    // ---- prep-independent prologue (overlaps with prep under PDL) ----
    // enc row (one float4 per thread)
    const float4 e4 = *(const float4*)(enc + ((long long)b * TT + t) * HH + 4 * q);

    // conv windows (SAME, zero pad) — broadcast loads, L1/L2-resident
    const float* pr = pitch  + (long long)b * TT;
    const float* er = energy + (long long)b * TT;
    const float pm1 = (t > 0)      ? pr[t - 1] : 0.f;
    const float p0  =                pr[t];
    const float pp1 = (t < TT - 1) ? pr[t + 1] : 0.f;
    const float em1 = (t > 0)      ? er[t - 1] : 0.f;
    const float e0  =                er[t];
    const float ep1 = (t < TT - 1) ? er[t + 1] : 0.f;

    // weights: [H][3] row-major -> 12 contiguous floats per float4-slot
    const float4* pwv = (const float4*)(pw + 12 * q);
    const float4 w0 = pwv[0], w1 = pwv[1], w2 = pwv[2];
    const float4* ewv = (const float4*)(ew + 12 * q);
    const float4 u0 = ewv[0], u1 = ewv[1], u2 = ewv[2];
    const float4 pbv = ((const float4*)pb)[q];
    const float4 ebv = ((const float4*)eb)[q];

    float4 res;
    res.x = e4.x + pbv.x + ebv.x
          + pm1 * w0.x + p0 * w0.y + pp1 * w0.z
          + em1 * u0.x + e0 * u0.y + ep1 * u0.z;
    res.y = e4.y + pbv.y + ebv.y
          + pm1 * w0.w + p0 * w1.x + pp1 * w1.y
          + em1 * u0.w + e0 * u1.x + ep1 * u1.y;
    res.z = e4.z + pbv.z + ebv.z
          + pm1 * w1.z + p0 * w1.w + pp1 * w2.x
          + em1 * u1.z + e0 * u1.w + ep1 * u2.x;
    res.w = e4.w + pbv.w + ebv.w
          + pm1 * w2.y + p0 * w2.z + pp1 * w2.w
          + em1 * u2.y + e0 * u2.z + ep1 * u2.w;

    // ---- dependent part: wait for prep, then read start and burst-store ----
    cudaGridDependencySynchronize();
    const int start = g_start[b * TT + t];
    const int n = min(start + rep, MEL) - start;
    if (n <= 0) return;

    // predicated store burst: reps < 8, all addresses independent,
    // stores issue back-to-back with no loop-carried dependency
    float4* dst = (float4*)out + ((long long)b * MEL + start) * H4 + q;
    #pragma unroll
    for (int j = 0; j < 7; ++j)
        if (j < n) __stcs(dst + (long long)j * H4, res);
    for (int j = 7; j < n; ++j)          // safety; never taken for this data
        __stcs(dst + (long long)j * H4, res);
}

extern "C" void kernel_launch(void* const* d_in, const int* in_sizes, int n_in,
                              void* d_out, int out_size)
{
    const float* enc    = (const float*)d_in[0];
    const float* pitch  = (const float*)d_in[1];
    const float* energy = (const float*)d_in[2];
    const float* pw     = (const float*)d_in[3];
    const float* pb     = (const float*)d_in[4];
    const float* ew     = (const float*)d_in[5];
    const float* eb     = (const float*)d_in[6];
    const int*   dur    = (const int*)d_in[7];
    float* out = (float*)d_out;

    const long long mainN = (long long)BB * MEL * HH;    // 50,331,648
    float* out_tail = ((long long)out_size >= mainN + BB) ? (out + mainN) : nullptr;

    prep_kernel<<<BB, PT>>>(dur, out_tail);

    // expand launched with programmatic dependent launch: starts while prep
    // is still running; the device-side sync gates only the g_start/g_dec reads.
    cudaLaunchConfig_t cfg = {};
    cfg.gridDim  = dim3(TT + ZB, BB, 1);
    cfg.blockDim = dim3(96, 1, 1);
    cfg.dynamicSmemBytes = 0;
    cfg.stream = 0;   // legacy default stream (matches harness capture)
    cudaLaunchAttribute attrs[1];
    attrs[0].id = cudaLaunchAttributeProgrammaticStreamSerialization;
    attrs[0].val.programmaticStreamSerializationAllowed = 1;
    cfg.attrs = attrs;
    cfg.numAttrs = 1;
    cudaLaunchKernelEx(&cfg, expand_kernel,
                       enc, pitch, energy, pw, pb, ew, eb, dur, out);
}